// round 4
// baseline (speedup 1.0000x reference)
#include <cuda_runtime.h>
#include <cuda_bf16.h>

// GaussianModel: cov = (R*diag(s)) (R*diag(s))^T per Gaussian.
// Inputs (metadata order): rotation_raw float32 [N,4], scaling_raw float32 [N,3]
// Output: cov float32 [N,3,3]
// Pure streaming map: 28 B in + 36 B out per element -> HBM-bound (~256 MB total).

__global__ __launch_bounds__(256)
void gaussian_cov_kernel(const float4* __restrict__ rot,
                         const float*  __restrict__ sc,
                         float*        __restrict__ out,
                         int n)
{
    int i = blockIdx.x * blockDim.x + threadIdx.x;
    if (i >= n) return;

    // 128-bit load of the quaternion (w, x, y, z)
    float4 q = __ldg(&rot[i]);
    float w = q.x, x = q.y, y = q.z, z = q.w;

    // R entries are quadratic in the normalized quaternion, so we can skip the
    // normalize: every "2*a*b" term becomes raw a*b * (2 / ||q||^2).
    float n2   = w*w + x*x + y*y + z*z;
    float inv2 = __fdividef(2.0f, n2);

    float xx = x*x*inv2, yy = y*y*inv2, zz = z*z*inv2;
    float xy = x*y*inv2, xz = x*z*inv2, yz = y*z*inv2;
    float wx = w*x*inv2, wy = w*y*inv2, wz = w*z*inv2;

    float r00 = 1.0f - yy - zz, r01 = xy - wz,        r02 = xz + wy;
    float r10 = xy + wz,        r11 = 1.0f - xx - zz, r12 = yz - wx;
    float r20 = xz - wy,        r21 = yz + wx,        r22 = 1.0f - xx - yy;

    // s = exp(scaling_raw); cov = sum_k s_k^2 * R[:,k] R[:,k]^T
    const float* sp = sc + 3 * i;
    float s0 = __expf(__ldg(sp + 0));
    float s1 = __expf(__ldg(sp + 1));
    float s2 = __expf(__ldg(sp + 2));
    float s00 = s0 * s0, s11 = s1 * s1, s22 = s2 * s2;

    float c00 = r00*r00*s00 + r01*r01*s11 + r02*r02*s22;
    float c01 = r00*r10*s00 + r01*r11*s11 + r02*r12*s22;
    float c02 = r00*r20*s00 + r01*r21*s11 + r02*r22*s22;
    float c11 = r10*r10*s00 + r11*r11*s11 + r12*r12*s22;
    float c12 = r10*r20*s00 + r11*r21*s11 + r12*r22*s22;
    float c22 = r20*r20*s00 + r21*r21*s11 + r22*r22*s22;

    // 9 consecutive 32-bit stores per thread: warp covers a contiguous
    // 1152-byte span -> fully sector-coalesced DRAM writes.
    float* o = out + 9 * i;
    o[0] = c00; o[1] = c01; o[2] = c02;
    o[3] = c01; o[4] = c11; o[5] = c12;
    o[6] = c02; o[7] = c12; o[8] = c22;
}

extern "C" void kernel_launch(void* const* d_in, const int* in_sizes, int n_in,
                              void* d_out, int out_size)
{
    const float4* rot = (const float4*)d_in[0];   // [N,4] float32
    const float*  sc  = (const float*) d_in[1];   // [N,3] float32
    float*        out = (float*)d_out;            // [N,3,3] float32

    int n = in_sizes[0] / 4;                      // element count of rotation_raw / 4
    int threads = 256;
    int blocks  = (n + threads - 1) / threads;
    gaussian_cov_kernel<<<blocks, threads>>>(rot, sc, out, n);
}

// round 5
// speedup vs baseline: 2.5986x; 2.5986x over previous
#include <cuda_runtime.h>
#include <cuda_bf16.h>

// GaussianModel: cov = (R*diag(s)) (R*diag(s))^T per Gaussian, N=4M.
// Inputs: rotation_raw float32 [N,4], scaling_raw float32 [N,3]
// Output: cov float32 [N,3,3]
//
// R4 change: R3 was L1tex-wavefront bound (scalar stride-36B stores = 9 lines
// per STG.32). Stage scaling-in and cov-out through shared memory so all
// global traffic is contiguous float4 (4 lines per warp-instruction, the
// minimum). Predicted ~8x fewer L1tex wavefronts -> DRAM-bound ~45-55us.

__global__ __launch_bounds__(256)
void gaussian_cov_kernel(const float4* __restrict__ rot,
                         const float*  __restrict__ sc,
                         float*        __restrict__ out,
                         int n)
{
    __shared__ float sh_s[256 * 3];     // staged scaling for this block
    __shared__ float sh_o[256 * 9];     // staged covariance output

    const int tid  = threadIdx.x;
    const int base = blockIdx.x * 256;  // first element handled by this block

    // ---- Stage scaling_raw: floats [3*base, 3*base+768), float4-aligned ----
    // (3*base = 768*blockIdx.x is a multiple of 4)
    {
        const int nf = 3 * n;
        const int f0 = 3 * base;
        if (tid < 192) {
            const int fi = f0 + 4 * tid;
            if (fi + 3 < nf) {
                ((float4*)sh_s)[tid] = ((const float4*)sc)[f0 / 4 + tid];
            } else {
                #pragma unroll
                for (int k = 0; k < 4; k++) {
                    int g = fi + k;
                    sh_s[4 * tid + k] = (g < nf) ? sc[g] : 0.0f;
                }
            }
        }
    }
    __syncthreads();

    // ---- Per-element math ----
    const int i = base + tid;
    if (i < n) {
        float4 q = __ldg(&rot[i]);               // LDG.128: 4 lines/warp (ideal)
        float w = q.x, x = q.y, y = q.z, z = q.w;

        // R is quadratic in the normalized quaternion: skip the normalize,
        // fold 2/||q||^2 into the cross terms.
        float n2   = w*w + x*x + y*y + z*z;
        float inv2 = __fdividef(2.0f, n2);

        float xx = x*x*inv2, yy = y*y*inv2, zz = z*z*inv2;
        float xy = x*y*inv2, xz = x*z*inv2, yz = y*z*inv2;
        float wx = w*x*inv2, wy = w*y*inv2, wz = w*z*inv2;

        float r00 = 1.0f - yy - zz, r01 = xy - wz,        r02 = xz + wy;
        float r10 = xy + wz,        r11 = 1.0f - xx - zz, r12 = yz - wx;
        float r20 = xz - wy,        r21 = yz + wx,        r22 = 1.0f - xx - yy;

        // s_k^2 = exp(2 * raw_k). Scalar LDS at stride 3: conflict-free.
        float s00 = __expf(2.0f * sh_s[3 * tid + 0]);
        float s11 = __expf(2.0f * sh_s[3 * tid + 1]);
        float s22 = __expf(2.0f * sh_s[3 * tid + 2]);

        float c00 = r00*r00*s00 + r01*r01*s11 + r02*r02*s22;
        float c01 = r00*r10*s00 + r01*r11*s11 + r02*r12*s22;
        float c02 = r00*r20*s00 + r01*r21*s11 + r02*r22*s22;
        float c11 = r10*r10*s00 + r11*r11*s11 + r12*r12*s22;
        float c12 = r10*r20*s00 + r11*r21*s11 + r12*r22*s22;
        float c22 = r20*r20*s00 + r21*r21*s11 + r22*r22*s22;

        // STS.32 at stride 9: gcd(9,32)=1 -> all 32 lanes hit distinct banks.
        float* o = sh_o + 9 * tid;
        o[0] = c00; o[1] = c01; o[2] = c02;
        o[3] = c01; o[4] = c11; o[5] = c12;
        o[6] = c02; o[7] = c12; o[8] = c22;
    }
    __syncthreads();

    // ---- Cooperative float4 store: floats [9*base, 9*base+2304) ----
    // (9*base = 2304*blockIdx.x is a multiple of 4)
    {
        const int nOutF = 9 * n;                 // 36M, fits in int
        const int ob    = 9 * base;
        const float4* src = (const float4*)sh_o;
        float4* dst = (float4*)(out + ob);
        #pragma unroll
        for (int k = tid; k < 576; k += 256) {   // 576 float4 per block
            const int fi = ob + 4 * k;
            if (fi + 3 < nOutF) {
                dst[k] = src[k];                 // STG.128: 4 lines/warp (ideal)
            } else {
                #pragma unroll
                for (int b = 0; b < 4; b++) {
                    int g = fi + b;
                    if (g < nOutF) out[g] = sh_o[4 * k + b];
                }
            }
        }
    }
}

extern "C" void kernel_launch(void* const* d_in, const int* in_sizes, int n_in,
                              void* d_out, int out_size)
{
    const float4* rot = (const float4*)d_in[0];   // [N,4] float32
    const float*  sc  = (const float*) d_in[1];   // [N,3] float32
    float*        out = (float*)d_out;            // [N,3,3] float32

    int n = in_sizes[0] / 4;
    int threads = 256;
    int blocks  = (n + threads - 1) / threads;
    gaussian_cov_kernel<<<blocks, threads>>>(rot, sc, out, n);
}